// round 13
// baseline (speedup 1.0000x reference)
#include <cuda_runtime.h>

#define N_MOLS  32768
#define N_ATOMS 4194304
#define THREADS 256
// 4 atoms per thread
#define N_THREADS_TOTAL (N_ATOMS / 4)
#define N_BLOCKS (N_THREADS_TOTAL / THREADS)

// Zero-invariant scratch accumulator: zero-initialized at module load; the
// publish epilogue restores it to zero every launch, so kernel_launch always
// sees it zeroed on entry. Lets the main kernel start with no prologue.
__device__ float g_scratch[N_MOLS];

__device__ __forceinline__ float tanh_approx(float x) {
    float y;
    asm("tanh.approx.f32 %0, %1;" : "=f"(y) : "f"(x));
    return y;
}

__global__ __launch_bounds__(THREADS) void sumpool_kernel(
    const float4* __restrict__ xyz4,     // N_ATOMS*3 floats viewed as float4
    const int4*   __restrict__ ids4,     // N_ATOMS ints viewed as int4
    const float*  __restrict__ w,        // 3 floats
    float4*       __restrict__ grad4)    // N_ATOMS*3 floats viewed as float4
{
    const int tid  = blockIdx.x * blockDim.x + threadIdx.x;
    const int lane = threadIdx.x & 31;

    const float w0 = __ldg(w + 0);
    const float w1 = __ldg(w + 1);
    const float w2 = __ldg(w + 2);

    // 4 atoms = 12 floats = 3 coalesced float4 loads + 1 int4 (front-batched, MLP=4)
    const float4 a = xyz4[tid * 3 + 0];
    const float4 b = xyz4[tid * 3 + 1];
    const float4 c = xyz4[tid * 3 + 2];
    const int4  id = ids4[tid];

    // atom k coords: atom0: a.x a.y a.z | atom1: a.w b.x b.y
    //                atom2: b.z b.w c.x | atom3: c.y c.z c.w
    const float t0 = tanh_approx(a.x * w0 + a.y * w1 + a.z * w2);
    const float t1 = tanh_approx(a.w * w0 + b.x * w1 + b.y * w2);
    const float t2 = tanh_approx(b.z * w0 + b.w * w1 + c.x * w2);
    const float t3 = tanh_approx(c.y * w0 + c.z * w1 + c.w * w2);

    const float g0 = 1.0f - t0 * t0;
    const float g1 = 1.0f - t1 * t1;
    const float g2 = 1.0f - t2 * t2;
    const float g3 = 1.0f - t3 * t3;

    grad4[tid * 3 + 0] = make_float4(g0 * w0, g0 * w1, g0 * w2, g1 * w0);
    grad4[tid * 3 + 1] = make_float4(g1 * w1, g1 * w2, g2 * w0, g2 * w1);
    grad4[tid * 3 + 2] = make_float4(g2 * w2, g3 * w0, g3 * w1, g3 * w2);

    // ---- segment sum of t0..t3 over sorted ids, into zero-invariant scratch ----
    int   cur = id.x;
    float s   = t0;
    if (id.y == cur) { s += t1; } else { atomicAdd(&g_scratch[cur], s); cur = id.y; s = t1; }
    if (id.z == cur) { s += t2; } else { atomicAdd(&g_scratch[cur], s); cur = id.z; s = t2; }
    if (id.w == cur) { s += t3; } else { atomicAdd(&g_scratch[cur], s); cur = id.w; s = t3; }

    // warp-level segmented reduction (ids sorted => equal-id lanes contiguous)
    #pragma unroll
    for (int off = 1; off < 32; off <<= 1) {
        const float v   = __shfl_down_sync(0xffffffffu, s,   off);
        const int   oid = __shfl_down_sync(0xffffffffu, cur, off);
        if (lane + off < 32 && oid == cur) s += v;
    }
    const int prev = __shfl_up_sync(0xffffffffu, cur, 1);
    if (lane == 0 || prev != cur) {
        atomicAdd(&g_scratch[cur], s);   // run leader flushes whole-run tail sum
    }
}

// Epilogue: publish scratch -> energy, restore scratch invariant (zero).
__global__ void publish_energy_kernel(float4* __restrict__ energy4) {
    const int i = blockIdx.x * blockDim.x + threadIdx.x;   // 8192 threads
    cudaGridDependencySynchronize();   // wait for main kernel's atomics
    float4* s4 = reinterpret_cast<float4*>(g_scratch);
    energy4[i] = s4[i];
    s4[i] = make_float4(0.f, 0.f, 0.f, 0.f);
}

extern "C" void kernel_launch(void* const* d_in, const int* in_sizes, int n_in,
                              void* d_out, int out_size) {
    const float4* xyz4 = (const float4*)d_in[0];
    const int4*   ids4 = (const int4*)d_in[1];
    const float*  w    = (const float*)d_in[2];

    float* energy = (float*)d_out;                      // [N_MOLS]
    float4* grad4 = (float4*)((float*)d_out + N_MOLS);  // [N_ATOMS*3] floats

    // Main kernel: no prologue, starts immediately.
    sumpool_kernel<<<N_BLOCKS, THREADS>>>(xyz4, ids4, w, grad4);

    // Epilogue with PDL: its launch overlaps the main kernel's tail wave;
    // gridDependencySynchronize inside orders it after main's completion.
    cudaLaunchConfig_t cfg = {};
    cfg.gridDim  = dim3((N_MOLS / 4) / 256, 1, 1);   // 32 blocks
    cfg.blockDim = dim3(256, 1, 1);
    cudaLaunchAttribute attrs[1];
    attrs[0].id = cudaLaunchAttributeProgrammaticStreamSerialization;
    attrs[0].val.programmaticStreamSerializationAllowed = 1;
    cfg.attrs    = attrs;
    cfg.numAttrs = 1;
    cudaLaunchKernelEx(&cfg, publish_energy_kernel, (float4*)energy);
}

// round 14
// speedup vs baseline: 1.0905x; 1.0905x over previous
#include <cuda_runtime.h>
#include <cstdint>

#define N_MOLS  32768
#define N_ATOMS 4194304
#define THREADS 256
#define APT     8                                // atoms per thread
#define N_THREADS_TOTAL (N_ATOMS / APT)          // 524288
#define N_BLOCKS (N_THREADS_TOTTAL_FIX 0)
#undef N_BLOCKS
#define N_BLOCKS (N_THREADS_TOTAL / THREADS)     // 2048

// Zero-invariant scratch accumulator (module-load zeroed; publish restores it).
__device__ float g_scratch[N_MOLS];

__device__ __forceinline__ float tanh_approx(float x) {
    float y;
    asm("tanh.approx.f32 %0, %1;" : "=f"(y) : "f"(x));
    return y;
}

// 256-bit global load with L2 evict_last (legal on .v8.b32 per ptxas).
__device__ __forceinline__ void ldg256_el(const void* p, uint32_t* r) {
    asm volatile(
        "ld.global.L2::evict_last.v8.b32 {%0,%1,%2,%3,%4,%5,%6,%7}, [%8];"
        : "=r"(r[0]), "=r"(r[1]), "=r"(r[2]), "=r"(r[3]),
          "=r"(r[4]), "=r"(r[5]), "=r"(r[6]), "=r"(r[7])
        : "l"(p));
}
// 256-bit global store with L2 evict_first.
__device__ __forceinline__ void stg256_ef(void* p, const uint32_t* r) {
    asm volatile(
        "st.global.L2::evict_first.v8.b32 [%0], {%1,%2,%3,%4,%5,%6,%7,%8};"
        :: "l"(p), "r"(r[0]), "r"(r[1]), "r"(r[2]), "r"(r[3]),
           "r"(r[4]), "r"(r[5]), "r"(r[6]), "r"(r[7]) : "memory");
}

__global__ __launch_bounds__(THREADS, 5) void sumpool_kernel(
    const float* __restrict__ xyz,      // N_ATOMS*3 floats
    const int*   __restrict__ ids,      // N_ATOMS ints
    const float* __restrict__ w,        // 3 floats
    float*       __restrict__ grad)     // N_ATOMS*3 floats
{
    const int tid  = blockIdx.x * blockDim.x + threadIdx.x;   // 0..524287
    const int lane = threadIdx.x & 31;

    const float w0 = __ldg(w + 0);
    const float w1 = __ldg(w + 1);
    const float w2 = __ldg(w + 2);

    // 8 atoms: 24 floats = 3x 256-bit loads, 8 ids = 1x 256-bit load (MLP=4 wide ops)
    uint32_t xr[24], idr[8];
    ldg256_el(xyz + (size_t)tid * 24 +  0, xr +  0);
    ldg256_el(xyz + (size_t)tid * 24 +  8, xr +  8);
    ldg256_el(xyz + (size_t)tid * 24 + 16, xr + 16);
    ldg256_el(ids + (size_t)tid * 8,       idr);

    const float* f  = reinterpret_cast<const float*>(xr);
    const int*   id = reinterpret_cast<const int*>(idr);

    float t[APT];
    uint32_t o[24];
    #pragma unroll
    for (int k = 0; k < APT; k++) {
        const float u = f[3*k] * w0 + f[3*k+1] * w1 + f[3*k+2] * w2;
        const float tk = tanh_approx(u);
        t[k] = tk;
        const float g = 1.0f - tk * tk;
        o[3*k]   = __float_as_uint(g * w0);
        o[3*k+1] = __float_as_uint(g * w1);
        o[3*k+2] = __float_as_uint(g * w2);
    }

    stg256_ef(grad + (size_t)tid * 24 +  0, o +  0);
    stg256_ef(grad + (size_t)tid * 24 +  8, o +  8);
    stg256_ef(grad + (size_t)tid * 24 + 16, o + 16);

    // ---- segment sum of t[0..7] over sorted ids, into zero-invariant scratch ----
    int   cur = id[0];
    float s   = t[0];
    #pragma unroll
    for (int k = 1; k < APT; k++) {
        if (id[k] == cur) { s += t[k]; }
        else { atomicAdd(&g_scratch[cur], s); cur = id[k]; s = t[k]; }
    }

    // warp-level segmented reduction (ids sorted => equal-id lanes contiguous)
    #pragma unroll
    for (int off = 1; off < 32; off <<= 1) {
        const float v   = __shfl_down_sync(0xffffffffu, s,   off);
        const int   oid = __shfl_down_sync(0xffffffffu, cur, off);
        if (lane + off < 32 && oid == cur) s += v;
    }
    const int prev = __shfl_up_sync(0xffffffffu, cur, 1);
    if (lane == 0 || prev != cur) {
        atomicAdd(&g_scratch[cur], s);
    }
}

// Epilogue: publish scratch -> energy, restore scratch invariant (zero).
__global__ void publish_energy_kernel(float4* __restrict__ energy4) {
    const int i = blockIdx.x * blockDim.x + threadIdx.x;   // 8192 threads
    cudaGridDependencySynchronize();   // wait for main kernel's atomics
    float4* s4 = reinterpret_cast<float4*>(g_scratch);
    energy4[i] = s4[i];
    s4[i] = make_float4(0.f, 0.f, 0.f, 0.f);
}

extern "C" void kernel_launch(void* const* d_in, const int* in_sizes, int n_in,
                              void* d_out, int out_size) {
    const float* xyz = (const float*)d_in[0];
    const int*   ids = (const int*)d_in[1];
    const float* w   = (const float*)d_in[2];

    float* energy = (float*)d_out;             // [N_MOLS]
    float* grad   = (float*)d_out + N_MOLS;    // [N_ATOMS*3]

    // Main kernel: no prologue, starts immediately.
    sumpool_kernel<<<N_BLOCKS, THREADS>>>(xyz, ids, w, grad);

    // Epilogue with PDL: launch overlaps main's tail wave; sync inside orders it.
    cudaLaunchConfig_t cfg = {};
    cfg.gridDim  = dim3((N_MOLS / 4) / 256, 1, 1);   // 32 blocks
    cfg.blockDim = dim3(256, 1, 1);
    cudaLaunchAttribute attrs[1];
    attrs[0].id = cudaLaunchAttributeProgrammaticStreamSerialization;
    attrs[0].val.programmaticStreamSerializationAllowed = 1;
    cfg.attrs    = attrs;
    cfg.numAttrs = 1;
    cudaLaunchKernelEx(&cfg, publish_energy_kernel, (float4*)energy);
}

// round 16
// speedup vs baseline: 1.0956x; 1.0047x over previous
#include <cuda_runtime.h>
#include <cstdint>

#define N_MOLS  32768
#define N_ATOMS 4194304
#define THREADS 256
#define APT     8                                // atoms per thread
#define N_THREADS_TOTAL (N_ATOMS / APT)          // 524288
#define N_BLOCKS (N_THREADS_TOTAL / THREADS)     // 2048

// Zero-invariant scratch accumulator (module-load zeroed; publish restores it).
__device__ float g_scratch[N_MOLS];

__device__ __forceinline__ float tanh_approx(float x) {
    float y;
    asm("tanh.approx.f32 %0, %1;" : "=f"(y) : "f"(x));
    return y;
}

// 256-bit global load with L2 evict_last.
__device__ __forceinline__ void ldg256_el(const void* p, uint32_t* r) {
    asm volatile(
        "ld.global.L2::evict_last.v8.b32 {%0,%1,%2,%3,%4,%5,%6,%7}, [%8];"
        : "=r"(r[0]), "=r"(r[1]), "=r"(r[2]), "=r"(r[3]),
          "=r"(r[4]), "=r"(r[5]), "=r"(r[6]), "=r"(r[7])
        : "l"(p));
}
// 256-bit global store with L2 evict_first.
__device__ __forceinline__ void stg256_ef(void* p, const uint32_t* r) {
    asm volatile(
        "st.global.L2::evict_first.v8.b32 [%0], {%1,%2,%3,%4,%5,%6,%7,%8};"
        :: "l"(p), "r"(r[0]), "r"(r[1]), "r"(r[2]), "r"(r[3]),
           "r"(r[4]), "r"(r[5]), "r"(r[6]), "r"(r[7]) : "memory");
}

__global__ __launch_bounds__(THREADS, 6) void sumpool_kernel(
    const float* __restrict__ xyz,      // N_ATOMS*3 floats
    const int*   __restrict__ ids,      // N_ATOMS ints
    const float* __restrict__ w,        // 3 floats
    float*       __restrict__ grad)     // N_ATOMS*3 floats
{
    const int tid  = blockIdx.x * blockDim.x + threadIdx.x;   // 0..524287
    const int lane = threadIdx.x & 31;

    const float w0 = __ldg(w + 0);
    const float w1 = __ldg(w + 1);
    const float w2 = __ldg(w + 2);

    // 8 atoms: 24 floats = 3x 256-bit loads, 8 ids = 1x 256-bit load
    uint32_t xr[24], idr[8];
    ldg256_el(xyz + (size_t)tid * 24 +  0, xr +  0);
    ldg256_el(xyz + (size_t)tid * 24 +  8, xr +  8);
    ldg256_el(xyz + (size_t)tid * 24 + 16, xr + 16);
    ldg256_el(ids + (size_t)tid * 8,       idr);

    const float* f  = reinterpret_cast<const float*>(xr);
    const int*   id = reinterpret_cast<const int*>(idr);

    float t[APT];
    uint32_t o[24];
    #pragma unroll
    for (int k = 0; k < APT; k++) {
        const float u  = f[3*k] * w0 + f[3*k+1] * w1 + f[3*k+2] * w2;
        const float tk = tanh_approx(u);
        t[k] = tk;
        const float g = 1.0f - tk * tk;
        o[3*k]   = __float_as_uint(g * w0);
        o[3*k+1] = __float_as_uint(g * w1);
        o[3*k+2] = __float_as_uint(g * w2);
    }

    stg256_ef(grad + (size_t)tid * 24 +  0, o +  0);
    stg256_ef(grad + (size_t)tid * 24 +  8, o +  8);
    stg256_ef(grad + (size_t)tid * 24 + 16, o + 16);

    // ---- segment sum of t[0..7] over sorted ids, into zero-invariant scratch ----
    int   cur = id[0];
    float s   = t[0];
    #pragma unroll
    for (int k = 1; k < APT; k++) {
        if (id[k] == cur) { s += t[k]; }
        else { atomicAdd(&g_scratch[cur], s); cur = id[k]; s = t[k]; }
    }

    // warp-level segmented reduction (ids sorted => equal-id lanes contiguous)
    #pragma unroll
    for (int off = 1; off < 32; off <<= 1) {
        const float v   = __shfl_down_sync(0xffffffffu, s,   off);
        const int   oid = __shfl_down_sync(0xffffffffu, cur, off);
        if (lane + off < 32 && oid == cur) s += v;
    }
    const int prev = __shfl_up_sync(0xffffffffu, cur, 1);
    if (lane == 0 || prev != cur) {
        atomicAdd(&g_scratch[cur], s);
    }
}

// Epilogue: publish scratch -> energy, restore scratch invariant (zero).
__global__ void publish_energy_kernel(float4* __restrict__ energy4) {
    const int i = blockIdx.x * blockDim.x + threadIdx.x;   // 8192 threads
    cudaGridDependencySynchronize();   // wait for main kernel's atomics
    float4* s4 = reinterpret_cast<float4*>(g_scratch);
    energy4[i] = s4[i];
    s4[i] = make_float4(0.f, 0.f, 0.f, 0.f);
}

extern "C" void kernel_launch(void* const* d_in, const int* in_sizes, int n_in,
                              void* d_out, int out_size) {
    const float* xyz = (const float*)d_in[0];
    const int*   ids = (const int*)d_in[1];
    const float* w   = (const float*)d_in[2];

    float* energy = (float*)d_out;             // [N_MOLS]
    float* grad   = (float*)d_out + N_MOLS;    // [N_ATOMS*3]

    // Main kernel: no prologue, starts immediately.
    sumpool_kernel<<<N_BLOCKS, THREADS>>>(xyz, ids, w, grad);

    // Epilogue with PDL: launch overlaps main's tail wave; sync inside orders it.
    cudaLaunchConfig_t cfg = {};
    cfg.gridDim  = dim3(64, 1, 1);
    cfg.blockDim = dim3(128, 1, 1);
    cudaLaunchAttribute attrs[1];
    attrs[0].id = cudaLaunchAttributeProgrammaticStreamSerialization;
    attrs[0].val.programmaticStreamSerializationAllowed = 1;
    cfg.attrs    = attrs;
    cfg.numAttrs = 1;
    cudaLaunchKernelEx(&cfg, publish_energy_kernel, (float4*)energy);
}

// round 17
// speedup vs baseline: 1.1827x; 1.0795x over previous
#include <cuda_runtime.h>
#include <cstdint>

#define N_MOLS  32768
#define N_ATOMS 4194304
#define THREADS 128
#define APT     8                                // atoms per thread
#define N_THREADS_TOTAL (N_ATOMS / APT)          // 524288
#define N_BLOCKS (N_THREADS_TOTAL / THREADS)     // 4096

// Zero-invariant scratch accumulator (module-load zeroed; publish restores it).
__device__ float g_scratch[N_MOLS];

__device__ __forceinline__ float tanh_approx(float x) {
    float y;
    asm("tanh.approx.f32 %0, %1;" : "=f"(y) : "f"(x));
    return y;
}

// 256-bit non-coherent global load with L2 evict_last (read-only data path).
__device__ __forceinline__ void ldg256_nc_el(const void* p, uint32_t* r) {
    asm volatile(
        "ld.global.nc.L2::evict_last.v8.b32 {%0,%1,%2,%3,%4,%5,%6,%7}, [%8];"
        : "=r"(r[0]), "=r"(r[1]), "=r"(r[2]), "=r"(r[3]),
          "=r"(r[4]), "=r"(r[5]), "=r"(r[6]), "=r"(r[7])
        : "l"(p));
}
// 256-bit global store with L2 evict_first.
__device__ __forceinline__ void stg256_ef(void* p, const uint32_t* r) {
    asm volatile(
        "st.global.L2::evict_first.v8.b32 [%0], {%1,%2,%3,%4,%5,%6,%7,%8};"
        :: "l"(p), "r"(r[0]), "r"(r[1]), "r"(r[2]), "r"(r[3]),
           "r"(r[4]), "r"(r[5]), "r"(r[6]), "r"(r[7]) : "memory");
}

__global__ __launch_bounds__(THREADS, 12) void sumpool_kernel(
    const float* __restrict__ xyz,      // N_ATOMS*3 floats
    const int*   __restrict__ ids,      // N_ATOMS ints
    const float* __restrict__ w,        // 3 floats
    float*       __restrict__ grad)     // N_ATOMS*3 floats
{
    const int tid  = blockIdx.x * blockDim.x + threadIdx.x;   // 0..524287
    const int lane = threadIdx.x & 31;

    const float w0 = __ldg(w + 0);
    const float w1 = __ldg(w + 1);
    const float w2 = __ldg(w + 2);

    // 8 atoms: 24 floats = 3x 256-bit loads, 8 ids = 1x 256-bit load
    uint32_t xr[24], idr[8];
    ldg256_nc_el(xyz + (size_t)tid * 24 +  0, xr +  0);
    ldg256_nc_el(xyz + (size_t)tid * 24 +  8, xr +  8);
    ldg256_nc_el(xyz + (size_t)tid * 24 + 16, xr + 16);
    ldg256_nc_el(ids + (size_t)tid * 8,       idr);

    const float* f  = reinterpret_cast<const float*>(xr);
    const int*   id = reinterpret_cast<const int*>(idr);

    float t[APT];
    uint32_t o[24];
    #pragma unroll
    for (int k = 0; k < APT; k++) {
        const float u  = f[3*k] * w0 + f[3*k+1] * w1 + f[3*k+2] * w2;
        const float tk = tanh_approx(u);
        t[k] = tk;
        const float g = 1.0f - tk * tk;
        o[3*k]   = __float_as_uint(g * w0);
        o[3*k+1] = __float_as_uint(g * w1);
        o[3*k+2] = __float_as_uint(g * w2);
    }

    stg256_ef(grad + (size_t)tid * 24 +  0, o +  0);
    stg256_ef(grad + (size_t)tid * 24 +  8, o +  8);
    stg256_ef(grad + (size_t)tid * 24 + 16, o + 16);

    // ---- segment sum of t[0..7] over sorted ids, into zero-invariant scratch ----
    int   cur = id[0];
    float s   = t[0];
    #pragma unroll
    for (int k = 1; k < APT; k++) {
        if (id[k] == cur) { s += t[k]; }
        else { atomicAdd(&g_scratch[cur], s); cur = id[k]; s = t[k]; }
    }

    // warp-level segmented reduction (ids sorted => equal-id lanes contiguous)
    #pragma unroll
    for (int off = 1; off < 32; off <<= 1) {
        const float v   = __shfl_down_sync(0xffffffffu, s,   off);
        const int   oid = __shfl_down_sync(0xffffffffu, cur, off);
        if (lane + off < 32 && oid == cur) s += v;
    }
    const int prev = __shfl_up_sync(0xffffffffu, cur, 1);
    if (lane == 0 || prev != cur) {
        atomicAdd(&g_scratch[cur], s);
    }
}

// Epilogue: publish scratch -> energy, restore scratch invariant (zero).
__global__ void publish_energy_kernel(float4* __restrict__ energy4) {
    const int i = blockIdx.x * blockDim.x + threadIdx.x;   // 8192 threads
    cudaGridDependencySynchronize();   // wait for main kernel's atomics
    float4* s4 = reinterpret_cast<float4*>(g_scratch);
    energy4[i] = s4[i];
    s4[i] = make_float4(0.f, 0.f, 0.f, 0.f);
}

extern "C" void kernel_launch(void* const* d_in, const int* in_sizes, int n_in,
                              void* d_out, int out_size) {
    const float* xyz = (const float*)d_in[0];
    const int*   ids = (const int*)d_in[1];
    const float* w   = (const float*)d_in[2];

    float* energy = (float*)d_out;             // [N_MOLS]
    float* grad   = (float*)d_out + N_MOLS;    // [N_ATOMS*3]

    // Main kernel: no prologue, starts immediately.
    sumpool_kernel<<<N_BLOCKS, THREADS>>>(xyz, ids, w, grad);

    // Epilogue with PDL: launch overlaps main's tail wave; sync inside orders it.
    cudaLaunchConfig_t cfg = {};
    cfg.gridDim  = dim3(64, 1, 1);
    cfg.blockDim = dim3(128, 1, 1);
    cudaLaunchAttribute attrs[1];
    attrs[0].id = cudaLaunchAttributeProgrammaticStreamSerialization;
    attrs[0].val.programmaticStreamSerializationAllowed = 1;
    cfg.attrs    = attrs;
    cfg.numAttrs = 1;
    cudaLaunchKernelEx(&cfg, publish_energy_kernel, (float4*)energy);
}